// round 10
// baseline (speedup 1.0000x reference)
#include <cuda_runtime.h>
#include <cuda_bf16.h>

#define N_MAX 100096
#define E_MAX 3200000
#define F 16
#define SCAN_TB 256

// Scratch (allocation-free rule: __device__ globals).
// Referenced from DEVICE code only (host-side reference = shadow symbol bug, R8).
__device__ __align__(16) float g_hs [N_MAX * F];  // layer-1 prescaled features
__device__ __align__(16) float g_acc[N_MAX * F];  // layer-2 prescaled features
__device__ float g_dinv[N_MAX];
__device__ int   g_cnt [N_MAX];    // in-degree (edges only)
__device__ int   g_off [N_MAX];    // CSR row start
__device__ int   g_cur [N_MAX];    // fill cursor
__device__ int   g_esrc[E_MAX];    // src ids grouped by dst
__device__ int   g_bsum[512];      // scan block partials

// ---------------------------------------------------------------------------
__global__ void k_cnt_zero(int n) {
    int i = blockIdx.x * blockDim.x + threadIdx.x;
    if (i < n) g_cnt[i] = 0;
}

// 4 edges per thread via int4 load
__global__ void k_deg_count(const int4* __restrict__ dst4, int E4, int E) {
    int i = blockIdx.x * blockDim.x + threadIdx.x;
    if (i >= E4) return;
    int4 d = __ldg(dst4 + i);
    int base = i * 4;
    if (base + 0 < E) atomicAdd(&g_cnt[d.x], 1);
    if (base + 1 < E) atomicAdd(&g_cnt[d.y], 1);
    if (base + 2 < E) atomicAdd(&g_cnt[d.z], 1);
    if (base + 3 < E) atomicAdd(&g_cnt[d.w], 1);
}

// --------------------------- 2-kernel exclusive scan -----------------------
__global__ void k_scanA(int n) {          // block sums + dinv
    __shared__ int sm[SCAN_TB];
    int t = threadIdx.x;
    int i = blockIdx.x * SCAN_TB + t;
    int c = (i < n) ? g_cnt[i] : 0;
    if (i < n) g_dinv[i] = rsqrtf((float)(c + 1));   // +1 self-loop
    sm[t] = c; __syncthreads();
    #pragma unroll
    for (int s = SCAN_TB / 2; s > 0; s >>= 1) {
        if (t < s) sm[t] += sm[t + s];
        __syncthreads();
    }
    if (t == 0) g_bsum[blockIdx.x] = sm[0];
}

// Each block: (a) reduce partials with index < blockIdx, (b) local excl scan.
__global__ void k_scanB(int n, int nblk) {
    __shared__ int sm[SCAN_TB];
    __shared__ int spre[SCAN_TB];
    int t = threadIdx.x;
    int i = blockIdx.x * SCAN_TB + t;

    // (a) prefix of earlier blocks (nblk <= 512 -> <=2 loads/thread)
    int p = 0;
    for (int j = t; j < blockIdx.x; j += SCAN_TB) p += g_bsum[j];
    spre[t] = p; __syncthreads();
    #pragma unroll
    for (int s = SCAN_TB / 2; s > 0; s >>= 1) {
        if (t < s) spre[t] += spre[t + s];
        __syncthreads();
    }
    int blk_pre = spre[0];
    __syncthreads();

    // (b) local Hillis-Steele inclusive scan
    int c = (i < n) ? g_cnt[i] : 0;
    sm[t] = c; __syncthreads();
    for (int s = 1; s < SCAN_TB; s <<= 1) {
        int add = (t >= s) ? sm[t - s] : 0;
        __syncthreads();
        sm[t] += add;
        __syncthreads();
    }
    if (i < n) {
        int excl = sm[t] - c + blk_pre;
        g_off[i] = excl;
        g_cur[i] = excl;
    }
}

// --------------------------- CSR fill --------------------------------------
__global__ void k_fill(const int4* __restrict__ src4,
                       const int4* __restrict__ dst4, int E4, int E) {
    int i = blockIdx.x * blockDim.x + threadIdx.x;
    if (i >= E4) return;
    int4 s = __ldg(src4 + i);
    int4 d = __ldg(dst4 + i);
    int base = i * 4;
    if (base + 0 < E) g_esrc[atomicAdd(&g_cur[d.x], 1)] = s.x;
    if (base + 1 < E) g_esrc[atomicAdd(&g_cur[d.y], 1)] = s.y;
    if (base + 2 < E) g_esrc[atomicAdd(&g_cur[d.z], 1)] = s.z;
    if (base + 3 < E) g_esrc[atomicAdd(&g_cur[d.w], 1)] = s.w;
}

// ---------------------------------------------------------------------------
// Layer-1 transform: g_hs[i] = (x[i] @ W1) * dinv[i]
__global__ void k_transform1(const float* __restrict__ xin,
                             const float* __restrict__ W, int n) {
    __shared__ float sW[F * F];
    int t = threadIdx.x;
    if (t < F * F) sW[t] = W[t];
    __syncthreads();

    int i = blockIdx.x * blockDim.x + t;
    if (i >= n) return;

    float dinv = g_dinv[i];
    float xv[F];
    const float4* xp = (const float4*)(xin + (size_t)i * F);
    #pragma unroll
    for (int q = 0; q < 4; q++) {
        float4 v = __ldg(xp + q);
        xv[4*q+0] = v.x; xv[4*q+1] = v.y; xv[4*q+2] = v.z; xv[4*q+3] = v.w;
    }
    float h[F];
    #pragma unroll
    for (int j = 0; j < F; j++) {
        float a = 0.0f;
        #pragma unroll
        for (int k = 0; k < F; k++)
            a = fmaf(xv[k], sW[k * F + j], a);
        h[j] = a * dinv;
    }
    float4* hp = (float4*)(g_hs + (size_t)i * F);
    #pragma unroll
    for (int q = 0; q < 4; q++)
        hp[q] = make_float4(h[4*q], h[4*q+1], h[4*q+2], h[4*q+3]);
}

// ---------------------------------------------------------------------------
// Warp-per-node gather core: 32 lanes = 8 edge slots x 4 quarters.
// Returns per-lane float4 = full quarter-sum (after butterfly reduction),
// identical across edge slots. c is warp-uniform -> no divergence.
__device__ __forceinline__ float4 warp_gather(const float* __restrict__ srcfeat,
                                              int node, int es, int q) {
    int off = __ldg(g_off + node);
    int c   = __ldg(g_cnt + node);
    const int* ep = g_esrc + off;

    float4 a = make_float4(0.f, 0.f, 0.f, 0.f);
    if (es == 0)   // self-loop
        a = __ldg((const float4*)(srcfeat + (size_t)node * F) + q);

    int k = 0;
    for (; k + 32 <= c; k += 32) {     // 4 independent load chains / thread
        int s0 = __ldg(ep + k +  0 + es);
        int s1 = __ldg(ep + k +  8 + es);
        int s2 = __ldg(ep + k + 16 + es);
        int s3 = __ldg(ep + k + 24 + es);
        float4 v0 = __ldg((const float4*)(srcfeat + (size_t)s0 * F) + q);
        float4 v1 = __ldg((const float4*)(srcfeat + (size_t)s1 * F) + q);
        float4 v2 = __ldg((const float4*)(srcfeat + (size_t)s2 * F) + q);
        float4 v3 = __ldg((const float4*)(srcfeat + (size_t)s3 * F) + q);
        a.x += (v0.x + v1.x) + (v2.x + v3.x);
        a.y += (v0.y + v1.y) + (v2.y + v3.y);
        a.z += (v0.z + v1.z) + (v2.z + v3.z);
        a.w += (v0.w + v1.w) + (v2.w + v3.w);
    }
    for (; k + 8 <= c; k += 8) {
        int s = __ldg(ep + k + es);
        float4 v = __ldg((const float4*)(srcfeat + (size_t)s * F) + q);
        a.x += v.x; a.y += v.y; a.z += v.z; a.w += v.w;
    }
    if (k + es < c) {                  // tail (<8 edges), predicated
        int s = __ldg(ep + k + es);
        float4 v = __ldg((const float4*)(srcfeat + (size_t)s * F) + q);
        a.x += v.x; a.y += v.y; a.z += v.z; a.w += v.w;
    }

    // reduce over edge-slot bits (lane bits [2:5))
    #pragma unroll
    for (int m = 4; m <= 16; m <<= 1) {
        a.x += __shfl_xor_sync(0xffffffffu, a.x, m);
        a.y += __shfl_xor_sync(0xffffffffu, a.y, m);
        a.z += __shfl_xor_sync(0xffffffffu, a.z, m);
        a.w += __shfl_xor_sync(0xffffffffu, a.w, m);
    }
    return a;
}

// Gather 1 + fused layer-2 transform:
// acc = gather(g_hs); y = relu(acc*dinv + b1); g_acc[node] = (y @ W2) * dinv
__global__ void k_gather_mid(const float* __restrict__ b1,
                             const float* __restrict__ W2, int n) {
    __shared__ float sW[F * F];
    int t = threadIdx.x;
    if (t < F * F) sW[t] = W2[t];
    __syncthreads();

    int node = (blockIdx.x * blockDim.x + t) >> 5;
    if (node >= n) return;
    int lane = t & 31;
    int es = lane >> 2, q = lane & 3;

    float4 a = warp_gather(g_hs, node, es, q);

    float dinv = __ldg(g_dinv + node);
    float4 y;
    y.x = fmaxf(fmaf(a.x, dinv, __ldg(b1 + q * 4 + 0)), 0.f);
    y.y = fmaxf(fmaf(a.y, dinv, __ldg(b1 + q * 4 + 1)), 0.f);
    y.z = fmaxf(fmaf(a.z, dinv, __ldg(b1 + q * 4 + 2)), 0.f);
    y.w = fmaxf(fmaf(a.w, dinv, __ldg(b1 + q * 4 + 3)), 0.f);

    // exchange quarters -> full 16-vector (values replicated across slots)
    float xv[F];
    int base = lane & ~3;
    #pragma unroll
    for (int p = 0; p < 4; p++) {
        xv[p*4+0] = __shfl_sync(0xffffffffu, y.x, base + p);
        xv[p*4+1] = __shfl_sync(0xffffffffu, y.y, base + p);
        xv[p*4+2] = __shfl_sync(0xffffffffu, y.z, base + p);
        xv[p*4+3] = __shfl_sync(0xffffffffu, y.w, base + p);
    }

    float h[4];
    #pragma unroll
    for (int j = 0; j < 4; j++) {
        int col = q * 4 + j;
        float s = 0.f;
        #pragma unroll
        for (int k = 0; k < F; k++)
            s = fmaf(xv[k], sW[k * F + col], s);
        h[j] = s * dinv;
    }
    if (es == 0)   // separate buffer: in-place g_hs write would race
        ((float4*)(g_acc + (size_t)node * F))[q] = make_float4(h[0], h[1], h[2], h[3]);
}

// Gather 2 + final epilogue: out = gather(g_acc)*dinv + b2
__global__ void k_gather_out(float* __restrict__ out,
                             const float* __restrict__ b2, int n) {
    int t = threadIdx.x;
    int node = (blockIdx.x * blockDim.x + t) >> 5;
    if (node >= n) return;
    int lane = t & 31;
    int es = lane >> 2, q = lane & 3;

    float4 a = warp_gather(g_acc, node, es, q);

    if (es == 0) {
        float dinv = __ldg(g_dinv + node);
        a.x = fmaf(a.x, dinv, __ldg(b2 + q * 4 + 0));
        a.y = fmaf(a.y, dinv, __ldg(b2 + q * 4 + 1));
        a.z = fmaf(a.z, dinv, __ldg(b2 + q * 4 + 2));
        a.w = fmaf(a.w, dinv, __ldg(b2 + q * 4 + 3));
        ((float4*)(out + (size_t)node * F))[q] = a;
    }
}

// ---------------------------------------------------------------------------
extern "C" void kernel_launch(void* const* d_in, const int* in_sizes, int n_in,
                              void* d_out, int out_size) {
    const float* x  = (const float*)d_in[0];
    const int*   ei = (const int*)  d_in[1];   // [2, E] int32
    const float* W1 = (const float*)d_in[2];
    const float* b1 = (const float*)d_in[3];
    const float* W2 = (const float*)d_in[4];
    const float* b2 = (const float*)d_in[5];
    float* out = (float*)d_out;

    const int n = in_sizes[0] / F;            // 100000
    const int E = in_sizes[1] / 2;            // 3200000
    const int* src = ei;
    const int* dst = ei + E;

    const int TB = 256;
    const int gn   = (n + TB - 1) / TB;
    const int E4   = (E + 3) / 4;
    const int ge4  = (E4 + TB - 1) / TB;
    const int nwpb = TB / 32;                 // warps (nodes) per block
    const int gw   = (n + nwpb - 1) / nwpb;   // warp-per-node grids
    const int nblk = (n + SCAN_TB - 1) / SCAN_TB;   // <= 512

    // CSR build (reused by both layers)
    k_cnt_zero  <<<gn, TB>>>(n);
    k_deg_count <<<ge4, TB>>>((const int4*)dst, E4, E);
    k_scanA     <<<nblk, SCAN_TB>>>(n);
    k_scanB     <<<nblk, SCAN_TB>>>(n, nblk);
    k_fill      <<<ge4, TB>>>((const int4*)src, (const int4*)dst, E4, E);

    // layer 1 transform, then gather+fused layer-2 transform, then final gather
    k_transform1<<<gn, TB>>>(x, W1, n);
    k_gather_mid<<<gw, TB>>>(b1, W2, n);
    k_gather_out<<<gw, TB>>>(out, b2, n);
}

// round 11
// speedup vs baseline: 1.2704x; 1.2704x over previous
#include <cuda_runtime.h>
#include <cuda_bf16.h>

#define N_MAX 100096
#define E_MAX 3200000
#define F 16
#define SCAN_TB 256

// Scratch (allocation-free rule: __device__ globals).
// Referenced from DEVICE code only (host-side reference = shadow symbol bug, R8).
__device__ __align__(16) float g_hs [N_MAX * F];  // layer-1 prescaled features
__device__ __align__(16) float g_acc[N_MAX * F];  // layer-2 prescaled features
__device__ float g_dinv[N_MAX];
__device__ int   g_cnt [N_MAX];    // in-degree (edges only)
__device__ int   g_off [N_MAX];    // CSR row start
__device__ int   g_cur [N_MAX];    // fill cursor
__device__ int   g_esrc[E_MAX];    // src ids grouped by dst
__device__ int   g_bsum[512];      // scan block partials

// ---------------------------------------------------------------------------
__global__ void k_cnt_zero(int n) {
    int i = blockIdx.x * blockDim.x + threadIdx.x;
    if (i < n) g_cnt[i] = 0;
}

// 4 edges per thread via int4 load
__global__ void k_deg_count(const int4* __restrict__ dst4, int E4, int E) {
    int i = blockIdx.x * blockDim.x + threadIdx.x;
    if (i >= E4) return;
    int4 d = __ldg(dst4 + i);
    int base = i * 4;
    if (base + 0 < E) atomicAdd(&g_cnt[d.x], 1);
    if (base + 1 < E) atomicAdd(&g_cnt[d.y], 1);
    if (base + 2 < E) atomicAdd(&g_cnt[d.z], 1);
    if (base + 3 < E) atomicAdd(&g_cnt[d.w], 1);
}

// --------------------------- 2-kernel exclusive scan -----------------------
__global__ void k_scanA(int n) {          // block sums + dinv
    __shared__ int sm[SCAN_TB];
    int t = threadIdx.x;
    int i = blockIdx.x * SCAN_TB + t;
    int c = (i < n) ? g_cnt[i] : 0;
    if (i < n) g_dinv[i] = rsqrtf((float)(c + 1));   // +1 self-loop
    sm[t] = c; __syncthreads();
    #pragma unroll
    for (int s = SCAN_TB / 2; s > 0; s >>= 1) {
        if (t < s) sm[t] += sm[t + s];
        __syncthreads();
    }
    if (t == 0) g_bsum[blockIdx.x] = sm[0];
}

// Each block: (a) reduce partials with index < blockIdx, (b) local excl scan.
__global__ void k_scanB(int n, int nblk) {
    __shared__ int sm[SCAN_TB];
    __shared__ int spre[SCAN_TB];
    int t = threadIdx.x;
    int i = blockIdx.x * SCAN_TB + t;

    int p = 0;
    for (int j = t; j < blockIdx.x; j += SCAN_TB) p += g_bsum[j];
    spre[t] = p; __syncthreads();
    #pragma unroll
    for (int s = SCAN_TB / 2; s > 0; s >>= 1) {
        if (t < s) spre[t] += spre[t + s];
        __syncthreads();
    }
    int blk_pre = spre[0];
    __syncthreads();

    int c = (i < n) ? g_cnt[i] : 0;
    sm[t] = c; __syncthreads();
    for (int s = 1; s < SCAN_TB; s <<= 1) {
        int add = (t >= s) ? sm[t - s] : 0;
        __syncthreads();
        sm[t] += add;
        __syncthreads();
    }
    if (i < n) {
        int excl = sm[t] - c + blk_pre;
        g_off[i] = excl;
        g_cur[i] = excl;
    }
}

// --------------------------- CSR fill --------------------------------------
__global__ void k_fill(const int4* __restrict__ src4,
                       const int4* __restrict__ dst4, int E4, int E) {
    int i = blockIdx.x * blockDim.x + threadIdx.x;
    if (i >= E4) return;
    int4 s = __ldg(src4 + i);
    int4 d = __ldg(dst4 + i);
    int base = i * 4;
    if (base + 0 < E) g_esrc[atomicAdd(&g_cur[d.x], 1)] = s.x;
    if (base + 1 < E) g_esrc[atomicAdd(&g_cur[d.y], 1)] = s.y;
    if (base + 2 < E) g_esrc[atomicAdd(&g_cur[d.z], 1)] = s.z;
    if (base + 3 < E) g_esrc[atomicAdd(&g_cur[d.w], 1)] = s.w;
}

// ---------------------------------------------------------------------------
// Layer-1 transform: g_hs[i] = (x[i] @ W1) * dinv[i]
__global__ void k_transform1(const float* __restrict__ xin,
                             const float* __restrict__ W, int n) {
    __shared__ float sW[F * F];
    int t = threadIdx.x;
    if (t < F * F) sW[t] = W[t];
    __syncthreads();

    int i = blockIdx.x * blockDim.x + t;
    if (i >= n) return;

    float dinv = g_dinv[i];
    float xv[F];
    const float4* xp = (const float4*)(xin + (size_t)i * F);
    #pragma unroll
    for (int q = 0; q < 4; q++) {
        float4 v = __ldg(xp + q);
        xv[4*q+0] = v.x; xv[4*q+1] = v.y; xv[4*q+2] = v.z; xv[4*q+3] = v.w;
    }
    float h[F];
    #pragma unroll
    for (int j = 0; j < F; j++) {
        float a = 0.0f;
        #pragma unroll
        for (int k = 0; k < F; k++)
            a = fmaf(xv[k], sW[k * F + j], a);
        h[j] = a * dinv;
    }
    float4* hp = (float4*)(g_hs + (size_t)i * F);
    #pragma unroll
    for (int q = 0; q < 4; q++)
        hp[q] = make_float4(h[4*q], h[4*q+1], h[4*q+2], h[4*q+3]);
}

// ---------------------------------------------------------------------------
// R9 gather core: 4 lanes per node (lane q owns quarter q), unroll x8.
// Returns this lane's quarter-sum incl. self-loop. Index words broadcast
// across the node's 4 lanes; feature loads coalesce to 64B rows.
__device__ __forceinline__ float4 quad_gather(const float* __restrict__ srcfeat,
                                              int node, int q) {
    int off = __ldg(g_off + node);
    int c   = __ldg(g_cnt + node);

    float4 a = __ldg((const float4*)(srcfeat + (size_t)node * F) + q);  // self-loop

    const int* ep = g_esrc + off;
    int k = 0;
    for (; k + 8 <= c; k += 8) {
        int s0 = __ldg(ep + k + 0);
        int s1 = __ldg(ep + k + 1);
        int s2 = __ldg(ep + k + 2);
        int s3 = __ldg(ep + k + 3);
        int s4 = __ldg(ep + k + 4);
        int s5 = __ldg(ep + k + 5);
        int s6 = __ldg(ep + k + 6);
        int s7 = __ldg(ep + k + 7);
        float4 v0 = __ldg((const float4*)(srcfeat + (size_t)s0 * F) + q);
        float4 v1 = __ldg((const float4*)(srcfeat + (size_t)s1 * F) + q);
        float4 v2 = __ldg((const float4*)(srcfeat + (size_t)s2 * F) + q);
        float4 v3 = __ldg((const float4*)(srcfeat + (size_t)s3 * F) + q);
        float4 v4 = __ldg((const float4*)(srcfeat + (size_t)s4 * F) + q);
        float4 v5 = __ldg((const float4*)(srcfeat + (size_t)s5 * F) + q);
        float4 v6 = __ldg((const float4*)(srcfeat + (size_t)s6 * F) + q);
        float4 v7 = __ldg((const float4*)(srcfeat + (size_t)s7 * F) + q);
        a.x += (v0.x + v1.x) + (v2.x + v3.x) + ((v4.x + v5.x) + (v6.x + v7.x));
        a.y += (v0.y + v1.y) + (v2.y + v3.y) + ((v4.y + v5.y) + (v6.y + v7.y));
        a.z += (v0.z + v1.z) + (v2.z + v3.z) + ((v4.z + v5.z) + (v6.z + v7.z));
        a.w += (v0.w + v1.w) + (v2.w + v3.w) + ((v4.w + v5.w) + (v6.w + v7.w));
    }
    for (; k < c; k++) {
        int s = __ldg(ep + k);
        float4 v = __ldg((const float4*)(srcfeat + (size_t)s * F) + q);
        a.x += v.x; a.y += v.y; a.z += v.z; a.w += v.w;
    }
    return a;
}

// Gather 1 + fused layer-2 transform:
// acc = gather(g_hs); y = relu(acc*dinv + b1); g_acc[node] = (y @ W2) * dinv
// Quarter exchange via 4-lane group shfl (lanes of a node are adjacent and
// share the node<n predicate, so the group mask never names an exited lane).
__global__ void k_gather_mid(const float* __restrict__ b1,
                             const float* __restrict__ W2, int n) {
    __shared__ float sW[F * F];
    int t = threadIdx.x;
    if (t < F * F) sW[t] = W2[t];
    __syncthreads();

    int gt = blockIdx.x * blockDim.x + t;
    int node = gt >> 2;
    int q = gt & 3;
    if (node >= n) return;

    float4 a = quad_gather(g_hs, node, q);

    float dinv = __ldg(g_dinv + node);
    float4 y;
    y.x = fmaxf(fmaf(a.x, dinv, __ldg(b1 + q * 4 + 0)), 0.f);
    y.y = fmaxf(fmaf(a.y, dinv, __ldg(b1 + q * 4 + 1)), 0.f);
    y.z = fmaxf(fmaf(a.z, dinv, __ldg(b1 + q * 4 + 2)), 0.f);
    y.w = fmaxf(fmaf(a.w, dinv, __ldg(b1 + q * 4 + 3)), 0.f);

    int lane = t & 31;
    int base = lane & ~3;
    unsigned gmask = 0xFu << base;
    float xv[F];
    #pragma unroll
    for (int p = 0; p < 4; p++) {
        xv[p*4+0] = __shfl_sync(gmask, y.x, base + p);
        xv[p*4+1] = __shfl_sync(gmask, y.y, base + p);
        xv[p*4+2] = __shfl_sync(gmask, y.z, base + p);
        xv[p*4+3] = __shfl_sync(gmask, y.w, base + p);
    }

    float h[4];
    #pragma unroll
    for (int j = 0; j < 4; j++) {
        int col = q * 4 + j;
        float s = 0.f;
        #pragma unroll
        for (int k = 0; k < F; k++)
            s = fmaf(xv[k], sW[k * F + col], s);
        h[j] = s * dinv;     // prescale by dinv[src] for layer-2 gather
    }
    // separate buffer: writing g_hs in place would race with other gatherers
    ((float4*)(g_acc + (size_t)node * F))[q] = make_float4(h[0], h[1], h[2], h[3]);
}

// Gather 2 + final epilogue: out = gather(g_acc)*dinv + b2
__global__ void k_gather_out(float* __restrict__ out,
                             const float* __restrict__ b2, int n) {
    int gt = blockIdx.x * blockDim.x + threadIdx.x;
    int node = gt >> 2;
    int q = gt & 3;
    if (node >= n) return;

    float4 a = quad_gather(g_acc, node, q);

    float dinv = __ldg(g_dinv + node);
    a.x = fmaf(a.x, dinv, __ldg(b2 + q * 4 + 0));
    a.y = fmaf(a.y, dinv, __ldg(b2 + q * 4 + 1));
    a.z = fmaf(a.z, dinv, __ldg(b2 + q * 4 + 2));
    a.w = fmaf(a.w, dinv, __ldg(b2 + q * 4 + 3));
    ((float4*)(out + (size_t)node * F))[q] = a;
}

// ---------------------------------------------------------------------------
extern "C" void kernel_launch(void* const* d_in, const int* in_sizes, int n_in,
                              void* d_out, int out_size) {
    const float* x  = (const float*)d_in[0];
    const int*   ei = (const int*)  d_in[1];   // [2, E] int32
    const float* W1 = (const float*)d_in[2];
    const float* b1 = (const float*)d_in[3];
    const float* W2 = (const float*)d_in[4];
    const float* b2 = (const float*)d_in[5];
    float* out = (float*)d_out;

    const int n = in_sizes[0] / F;            // 100000
    const int E = in_sizes[1] / 2;            // 3200000
    const int* src = ei;
    const int* dst = ei + E;

    const int TB = 256;
    const int gn   = (n + TB - 1) / TB;
    const int E4   = (E + 3) / 4;
    const int ge4  = (E4 + TB - 1) / TB;
    const int geg  = (n * 4 + TB - 1) / TB;   // gather: 4 threads per node
    const int nblk = (n + SCAN_TB - 1) / SCAN_TB;   // <= 512

    // CSR build (reused by both layers)
    k_cnt_zero  <<<gn, TB>>>(n);
    k_deg_count <<<ge4, TB>>>((const int4*)dst, E4, E);
    k_scanA     <<<nblk, SCAN_TB>>>(n);
    k_scanB     <<<nblk, SCAN_TB>>>(n, nblk);
    k_fill      <<<ge4, TB>>>((const int4*)src, (const int4*)dst, E4, E);

    // layer 1 transform, gather + fused layer-2 transform, final gather
    k_transform1<<<gn, TB>>>(x, W1, n);
    k_gather_mid<<<geg, TB>>>(b1, W2, n);
    k_gather_out<<<geg, TB>>>(out, b2, n);
}

// round 12
// speedup vs baseline: 1.3446x; 1.0584x over previous
#include <cuda_runtime.h>
#include <cuda_bf16.h>

#define N_MAX 100096
#define E_MAX 3500096   // E + up to 3 padding slots per node (4-aligned rows)
#define F 16
#define SCAN_TB 256

// Scratch (allocation-free rule: __device__ globals).
// Referenced from DEVICE code only (host-side reference = shadow symbol bug, R8).
__device__ __align__(16) float g_hs [N_MAX * F];  // layer-1 prescaled features
__device__ __align__(16) float g_acc[N_MAX * F];  // layer-2 prescaled features
__device__ float g_dinv[N_MAX];
__device__ int   g_cnt [N_MAX];    // in-degree (edges only); re-zeroed by gather_out
__device__ int   g_off [N_MAX];    // CSR row start (16B-aligned rows)
__device__ int   g_cur [N_MAX];    // fill cursor
__device__ __align__(16) int g_esrc[E_MAX];  // src ids grouped by dst (padded rows)
__device__ int   g_bsum[512];      // scan block partials

// ---------------------------------------------------------------------------
// 4 edges per thread via int4 load. g_cnt is zero at entry (invariant).
__global__ void k_deg_count(const int4* __restrict__ dst4, int E4, int E) {
    int i = blockIdx.x * blockDim.x + threadIdx.x;
    if (i >= E4) return;
    int4 d = __ldg(dst4 + i);
    int base = i * 4;
    if (base + 0 < E) atomicAdd(&g_cnt[d.x], 1);
    if (base + 1 < E) atomicAdd(&g_cnt[d.y], 1);
    if (base + 2 < E) atomicAdd(&g_cnt[d.z], 1);
    if (base + 3 < E) atomicAdd(&g_cnt[d.w], 1);
}

// --------------------------- warp-shuffle scan ------------------------------
// scanA: per-block sum of ALIGNED counts + dinv from real counts.
__global__ void k_scanA(int n) {
    __shared__ int ws[SCAN_TB / 32];
    int t = threadIdx.x, lane = t & 31, wid = t >> 5;
    int i = blockIdx.x * SCAN_TB + t;
    int c = (i < n) ? g_cnt[i] : 0;
    if (i < n) g_dinv[i] = rsqrtf((float)(c + 1));   // +1 self-loop
    int cal = (c + 3) & ~3;
    #pragma unroll
    for (int m = 16; m; m >>= 1) cal += __shfl_xor_sync(0xffffffffu, cal, m);
    if (lane == 0) ws[wid] = cal;
    __syncthreads();
    if (t == 0) {
        int s = 0;
        #pragma unroll
        for (int w = 0; w < SCAN_TB / 32; w++) s += ws[w];
        g_bsum[blockIdx.x] = s;
    }
}

// scanB: block prefix (reduce earlier partials) + local exclusive scan of
// aligned counts, via warp shuffles (3 barriers total).
__global__ void k_scanB(int n, int nblk) {
    __shared__ int s_pre[SCAN_TB / 32];
    __shared__ int ws[SCAN_TB / 32];
    int t = threadIdx.x, lane = t & 31, wid = t >> 5;
    int i = blockIdx.x * SCAN_TB + t;

    // prefix of earlier blocks (nblk <= 512 -> <=2 loads/thread)
    int p = 0;
    for (int j = t; j < blockIdx.x; j += SCAN_TB) p += g_bsum[j];
    #pragma unroll
    for (int m = 16; m; m >>= 1) p += __shfl_xor_sync(0xffffffffu, p, m);
    if (lane == 0) s_pre[wid] = p;
    __syncthreads();
    int blk_pre = 0;
    #pragma unroll
    for (int w = 0; w < SCAN_TB / 32; w++) blk_pre += s_pre[w];

    // local scan of aligned counts
    int c = (i < n) ? g_cnt[i] : 0;
    int cal = (c + 3) & ~3;
    int v = cal;
    #pragma unroll
    for (int m = 1; m < 32; m <<= 1) {
        int u = __shfl_up_sync(0xffffffffu, v, m);
        if (lane >= m) v += u;
    }
    if (lane == 31) ws[wid] = v;
    __syncthreads();
    int wpre = 0;
    for (int w = 0; w < wid; w++) wpre += ws[w];

    if (i < n) {
        int excl = (v - cal) + wpre + blk_pre;   // 4-aligned by construction
        g_off[i] = excl;
        g_cur[i] = excl;
    }
}

// --------------------------- CSR fill --------------------------------------
__global__ void k_fill(const int4* __restrict__ src4,
                       const int4* __restrict__ dst4, int E4, int E) {
    int i = blockIdx.x * blockDim.x + threadIdx.x;
    if (i >= E4) return;
    int4 s = __ldg(src4 + i);
    int4 d = __ldg(dst4 + i);
    int base = i * 4;
    if (base + 0 < E) g_esrc[atomicAdd(&g_cur[d.x], 1)] = s.x;
    if (base + 1 < E) g_esrc[atomicAdd(&g_cur[d.y], 1)] = s.y;
    if (base + 2 < E) g_esrc[atomicAdd(&g_cur[d.z], 1)] = s.z;
    if (base + 3 < E) g_esrc[atomicAdd(&g_cur[d.w], 1)] = s.w;
}

// ---------------------------------------------------------------------------
// Layer-1 transform: g_hs[i] = (x[i] @ W1) * dinv[i]
__global__ void k_transform1(const float* __restrict__ xin,
                             const float* __restrict__ W, int n) {
    __shared__ float sW[F * F];
    int t = threadIdx.x;
    if (t < F * F) sW[t] = W[t];
    __syncthreads();

    int i = blockIdx.x * blockDim.x + t;
    if (i >= n) return;

    float dinv = g_dinv[i];
    float xv[F];
    const float4* xp = (const float4*)(xin + (size_t)i * F);
    #pragma unroll
    for (int q = 0; q < 4; q++) {
        float4 v = __ldg(xp + q);
        xv[4*q+0] = v.x; xv[4*q+1] = v.y; xv[4*q+2] = v.z; xv[4*q+3] = v.w;
    }
    float h[F];
    #pragma unroll
    for (int j = 0; j < F; j++) {
        float a = 0.0f;
        #pragma unroll
        for (int k = 0; k < F; k++)
            a = fmaf(xv[k], sW[k * F + j], a);
        h[j] = a * dinv;
    }
    float4* hp = (float4*)(g_hs + (size_t)i * F);
    #pragma unroll
    for (int q = 0; q < 4; q++)
        hp[q] = make_float4(h[4*q], h[4*q+1], h[4*q+2], h[4*q+3]);
}

// ---------------------------------------------------------------------------
// Gather core: 4 lanes per node (lane q owns quarter q), unroll x8.
// Index loads vectorized to int4 (row starts 16B-aligned): 2 vector loads per
// 8-edge chunk instead of 8 scalar -> ~4x fewer index wavefronts at L1tex.
__device__ __forceinline__ float4 quad_gather(const float* __restrict__ srcfeat,
                                              int node, int q, int c) {
    int off = __ldg(g_off + node);

    float4 a = __ldg((const float4*)(srcfeat + (size_t)node * F) + q);  // self-loop

    const int* ep = g_esrc + off;   // 16B-aligned
    int k = 0;
    for (; k + 8 <= c; k += 8) {
        int4 ia = __ldg((const int4*)(ep + k));
        int4 ib = __ldg((const int4*)(ep + k + 4));
        float4 v0 = __ldg((const float4*)(srcfeat + (size_t)ia.x * F) + q);
        float4 v1 = __ldg((const float4*)(srcfeat + (size_t)ia.y * F) + q);
        float4 v2 = __ldg((const float4*)(srcfeat + (size_t)ia.z * F) + q);
        float4 v3 = __ldg((const float4*)(srcfeat + (size_t)ia.w * F) + q);
        float4 v4 = __ldg((const float4*)(srcfeat + (size_t)ib.x * F) + q);
        float4 v5 = __ldg((const float4*)(srcfeat + (size_t)ib.y * F) + q);
        float4 v6 = __ldg((const float4*)(srcfeat + (size_t)ib.z * F) + q);
        float4 v7 = __ldg((const float4*)(srcfeat + (size_t)ib.w * F) + q);
        a.x += (v0.x + v1.x) + (v2.x + v3.x) + ((v4.x + v5.x) + (v6.x + v7.x));
        a.y += (v0.y + v1.y) + (v2.y + v3.y) + ((v4.y + v5.y) + (v6.y + v7.y));
        a.z += (v0.z + v1.z) + (v2.z + v3.z) + ((v4.z + v5.z) + (v6.z + v7.z));
        a.w += (v0.w + v1.w) + (v2.w + v3.w) + ((v4.w + v5.w) + (v6.w + v7.w));
    }
    if (k + 4 <= c) {
        int4 ia = __ldg((const int4*)(ep + k));
        float4 v0 = __ldg((const float4*)(srcfeat + (size_t)ia.x * F) + q);
        float4 v1 = __ldg((const float4*)(srcfeat + (size_t)ia.y * F) + q);
        float4 v2 = __ldg((const float4*)(srcfeat + (size_t)ia.z * F) + q);
        float4 v3 = __ldg((const float4*)(srcfeat + (size_t)ia.w * F) + q);
        a.x += (v0.x + v1.x) + (v2.x + v3.x);
        a.y += (v0.y + v1.y) + (v2.y + v3.y);
        a.z += (v0.z + v1.z) + (v2.z + v3.z);
        a.w += (v0.w + v1.w) + (v2.w + v3.w);
        k += 4;
    }
    for (; k < c; k++) {
        int s = __ldg(ep + k);
        float4 v = __ldg((const float4*)(srcfeat + (size_t)s * F) + q);
        a.x += v.x; a.y += v.y; a.z += v.z; a.w += v.w;
    }
    return a;
}

// Gather 1 + fused layer-2 transform:
// acc = gather(g_hs); y = relu(acc*dinv + b1); g_acc[node] = (y @ W2) * dinv
__global__ void k_gather_mid(const float* __restrict__ b1,
                             const float* __restrict__ W2, int n) {
    __shared__ float sW[F * F];
    int t = threadIdx.x;
    if (t < F * F) sW[t] = W2[t];
    __syncthreads();

    int gt = blockIdx.x * blockDim.x + t;
    int node = gt >> 2;
    int q = gt & 3;
    if (node >= n) return;

    int c = __ldg(g_cnt + node);
    float4 a = quad_gather(g_hs, node, q, c);

    float dinv = __ldg(g_dinv + node);
    float4 y;
    y.x = fmaxf(fmaf(a.x, dinv, __ldg(b1 + q * 4 + 0)), 0.f);
    y.y = fmaxf(fmaf(a.y, dinv, __ldg(b1 + q * 4 + 1)), 0.f);
    y.z = fmaxf(fmaf(a.z, dinv, __ldg(b1 + q * 4 + 2)), 0.f);
    y.w = fmaxf(fmaf(a.w, dinv, __ldg(b1 + q * 4 + 3)), 0.f);

    // 4-lane group quarter exchange (lanes of a node share the node<n guard)
    int lane = t & 31;
    int base = lane & ~3;
    unsigned gmask = 0xFu << base;
    float xv[F];
    #pragma unroll
    for (int p = 0; p < 4; p++) {
        xv[p*4+0] = __shfl_sync(gmask, y.x, base + p);
        xv[p*4+1] = __shfl_sync(gmask, y.y, base + p);
        xv[p*4+2] = __shfl_sync(gmask, y.z, base + p);
        xv[p*4+3] = __shfl_sync(gmask, y.w, base + p);
    }

    float h[4];
    #pragma unroll
    for (int j = 0; j < 4; j++) {
        int col = q * 4 + j;
        float s = 0.f;
        #pragma unroll
        for (int k = 0; k < F; k++)
            s = fmaf(xv[k], sW[k * F + col], s);
        h[j] = s * dinv;     // prescale by dinv[src] for layer-2 gather
    }
    ((float4*)(g_acc + (size_t)node * F))[q] = make_float4(h[0], h[1], h[2], h[3]);
}

// Gather 2 + final epilogue: out = gather(g_acc)*dinv + b2.
// Also restores the g_cnt==0 invariant for the next graph replay.
__global__ void k_gather_out(float* __restrict__ out,
                             const float* __restrict__ b2, int n) {
    int gt = blockIdx.x * blockDim.x + threadIdx.x;
    int node = gt >> 2;
    int q = gt & 3;
    if (node >= n) return;

    int c = __ldg(g_cnt + node);
    float4 a = quad_gather(g_acc, node, q, c);
    if (q == 0) g_cnt[node] = 0;    // re-zero for next replay (after last read)

    float dinv = __ldg(g_dinv + node);
    a.x = fmaf(a.x, dinv, __ldg(b2 + q * 4 + 0));
    a.y = fmaf(a.y, dinv, __ldg(b2 + q * 4 + 1));
    a.z = fmaf(a.z, dinv, __ldg(b2 + q * 4 + 2));
    a.w = fmaf(a.w, dinv, __ldg(b2 + q * 4 + 3));
    ((float4*)(out + (size_t)node * F))[q] = a;
}

// ---------------------------------------------------------------------------
extern "C" void kernel_launch(void* const* d_in, const int* in_sizes, int n_in,
                              void* d_out, int out_size) {
    const float* x  = (const float*)d_in[0];
    const int*   ei = (const int*)  d_in[1];   // [2, E] int32
    const float* W1 = (const float*)d_in[2];
    const float* b1 = (const float*)d_in[3];
    const float* W2 = (const float*)d_in[4];
    const float* b2 = (const float*)d_in[5];
    float* out = (float*)d_out;

    const int n = in_sizes[0] / F;            // 100000
    const int E = in_sizes[1] / 2;            // 3200000
    const int* src = ei;
    const int* dst = ei + E;

    const int TB = 256;
    const int gn   = (n + TB - 1) / TB;
    const int E4   = (E + 3) / 4;
    const int ge4  = (E4 + TB - 1) / TB;
    const int geg  = (n * 4 + TB - 1) / TB;   // gather: 4 threads per node
    const int nblk = (n + SCAN_TB - 1) / SCAN_TB;   // <= 512

    // CSR build (g_cnt==0 invariant maintained by k_gather_out)
    k_deg_count <<<ge4, TB>>>((const int4*)dst, E4, E);
    k_scanA     <<<nblk, SCAN_TB>>>(n);
    k_scanB     <<<nblk, SCAN_TB>>>(n, nblk);
    k_fill      <<<ge4, TB>>>((const int4*)src, (const int4*)dst, E4, E);

    // layer 1 transform, gather + fused layer-2 transform, final gather
    k_transform1<<<gn, TB>>>(x, W1, n);
    k_gather_mid<<<geg, TB>>>(b1, W2, n);
    k_gather_out<<<geg, TB>>>(out, b2, n);
}